// round 9
// baseline (speedup 1.0000x reference)
#include <cuda_runtime.h>
#include <math.h>

// Problem constants
#define BATCH   4
#define TT      4096
#define EE      2048
#define DD      1024
#define GDIM    4096          // 4*DD gate rows
#define MOUT    2
#define KINW    2048          // input width per layer (E for l0, 2*DD for l1)

// Recurrence persistent-kernel config
#define RGRID    148          // <= SM count -> guaranteed co-resident
#define RTHREADS 256
#define NUNITS   (2*DD)       // dirs * D hidden units
#define UPB      ((NUNITS + RGRID - 1)/RGRID)   // 14 units per block

// ---------------- scratch (static device arrays only; no allocation) ------
__device__ __align__(128) float g_x   [BATCH*TT*KINW];      // layer input
__device__ __align__(128) float g_gx  [2u*BATCH*TT*GDIM];   // gate preacts, scan order, both dirs
__device__ __align__(128) float g_hL  [BATCH*TT*DD];
__device__ __align__(128) float g_hR  [BATCH*TT*DD];
__device__ __align__(128) float g_hcur[2][2*BATCH*DD];      // double-buffered current h
__device__ float g_wv  [BATCH*TT];
__device__ float g_att [BATCH*TT];
__device__ float g_ctxtL[BATCH*DD];
__device__ float g_ctxtR[BATCH*DD];
__device__ unsigned int g_barCount;
__device__ volatile unsigned int g_barEpoch;

// ---------------- embedding gather ----------------
__global__ void k_embed(const int* __restrict__ toks, const float* __restrict__ emb) {
    int idx = blockIdx.x * blockDim.x + threadIdx.x;      // float4 granularity
    const int total = BATCH*TT*(EE/4);
    if (idx >= total) return;
    int row = idx / (EE/4);
    int c   = idx - row*(EE/4);
    int tok = toks[row];
    reinterpret_cast<float4*>(g_x)[idx] =
        reinterpret_cast<const float4*>(emb + (size_t)tok*EE)[c];
}

// ---------------- gx GEMM: gx[d][b][s][n] = x[b][srow] . W[n] + bias -------
// srow = d ? T-1-s : s  (dir-1 consumes reversed input in scan order)
__global__ __launch_bounds__(256) void k_gemm(const float* __restrict__ Wxh,
                                              const float* __restrict__ bxh,
                                              const float* __restrict__ bhh,
                                              int layer) {
    const int d     = blockIdx.z;
    const int nBase = blockIdx.x * 64;
    const int mBase = blockIdx.y * 128;

    const float* W  = Wxh + (size_t)(layer*2 + d) * GDIM * KINW;
    const float* bx = bxh + (size_t)(layer*2 + d) * GDIM;
    const float* bh = bhh + (size_t)(layer*2 + d) * GDIM;

    __shared__ float As[16][128];
    __shared__ float Bs[16][64];

    const int tid  = threadIdx.x;
    const int aRow = tid >> 1;            // 0..127
    const int aKc  = (tid & 1) * 8;       // 0 or 8
    const int wRow = tid & 63;            // 0..63
    const int wKc  = (tid >> 6) * 4;      // 0,4,8,12

    const int bIdx  = mBase >> 12;        // T=4096: a 128-row tile never crosses batch
    const int sBase = mBase & (TT-1);

    const float* Arow;
    {
        int s    = sBase + aRow;
        int srow = d ? (TT-1-s) : s;
        Arow = g_x + ((size_t)bIdx*TT + srow)*KINW;
    }
    const float* Wrow = W + (size_t)(nBase + wRow)*KINW;

    float acc[8][4];
    #pragma unroll
    for (int i=0;i<8;i++)
        #pragma unroll
        for (int j=0;j<4;j++) acc[i][j]=0.f;

    const int ty = tid >> 4;   // 0..15, 8 M-rows each
    const int tx = tid & 15;   // 0..15, 4 N-cols each

    float4 ca0 = *reinterpret_cast<const float4*>(Arow + aKc);
    float4 ca1 = *reinterpret_cast<const float4*>(Arow + aKc + 4);
    float4 cw0 = *reinterpret_cast<const float4*>(Wrow + wKc);

    for (int k0 = 0; k0 < KINW; k0 += 16) {
        As[aKc+0][aRow]=ca0.x; As[aKc+1][aRow]=ca0.y; As[aKc+2][aRow]=ca0.z; As[aKc+3][aRow]=ca0.w;
        As[aKc+4][aRow]=ca1.x; As[aKc+5][aRow]=ca1.y; As[aKc+6][aRow]=ca1.z; As[aKc+7][aRow]=ca1.w;
        Bs[wKc+0][wRow]=cw0.x; Bs[wKc+1][wRow]=cw0.y; Bs[wKc+2][wRow]=cw0.z; Bs[wKc+3][wRow]=cw0.w;
        __syncthreads();

        const int kn = (k0 + 16 < KINW) ? (k0 + 16) : 0;   // harmless dummy reload on last iter
        ca0 = *reinterpret_cast<const float4*>(Arow + kn + aKc);
        ca1 = *reinterpret_cast<const float4*>(Arow + kn + aKc + 4);
        cw0 = *reinterpret_cast<const float4*>(Wrow + kn + wKc);

        #pragma unroll
        for (int kk = 0; kk < 16; ++kk) {
            float4 fa0 = *reinterpret_cast<const float4*>(&As[kk][ty*8]);
            float4 fa1 = *reinterpret_cast<const float4*>(&As[kk][ty*8+4]);
            float4 fb  = *reinterpret_cast<const float4*>(&Bs[kk][tx*4]);
            float a[8] = {fa0.x,fa0.y,fa0.z,fa0.w,fa1.x,fa1.y,fa1.z,fa1.w};
            float bb[4]= {fb.x,fb.y,fb.z,fb.w};
            #pragma unroll
            for (int i=0;i<8;i++)
                #pragma unroll
                for (int j=0;j<4;j++)
                    acc[i][j] = fmaf(a[i], bb[j], acc[i][j]);
        }
        __syncthreads();
    }

    float bias[4];
    #pragma unroll
    for (int j=0;j<4;j++) bias[j] = bx[nBase+tx*4+j] + bh[nBase+tx*4+j];

    #pragma unroll
    for (int i=0;i<8;i++) {
        size_t off = ((size_t)(d*BATCH + bIdx)*TT + sBase + ty*8 + i)*(size_t)GDIM + nBase + tx*4;
        float4 v = make_float4(acc[i][0]+bias[0], acc[i][1]+bias[1],
                               acc[i][2]+bias[2], acc[i][3]+bias[3]);
        *reinterpret_cast<float4*>(g_gx + off) = v;
    }
}

// ---------------- grid-wide software barrier (all blocks co-resident) ------
__device__ __forceinline__ void grid_barrier(unsigned int* localEpoch) {
    __syncthreads();
    if (threadIdx.x == 0) {
        unsigned int e = *localEpoch;
        __threadfence();
        if (atomicAdd(&g_barCount, 1u) == (unsigned)gridDim.x - 1u) {
            g_barCount = 0u;
            __threadfence();
            g_barEpoch = e + 1u;
        } else {
            while (g_barEpoch == e) { __nanosleep(32); }
        }
        *localEpoch = e + 1u;
    }
    __syncthreads();
}

// ---------------- persistent biLSTM recurrence over T steps ----------------
__global__ __launch_bounds__(RTHREADS) void k_recur(const float* __restrict__ Whh, int layer) {
    __shared__ float h_sm[2*BATCH*DD];   // 32 KB: [d][b][k]
    unsigned int localEpoch = g_barEpoch;
    const int tid  = threadIdx.x;
    const int warp = tid >> 5;
    const int lane = tid & 31;

    // zero h buffer 0 (read at t=0)
    for (int i = blockIdx.x*RTHREADS + tid; i < 2*BATCH*DD; i += RGRID*RTHREADS)
        g_hcur[0][i] = 0.f;
    __threadfence();
    grid_barrier(&localEpoch);

    const int u0 = blockIdx.x * UPB;
    int nLocal = NUNITS - u0;
    if (nLocal > UPB) nLocal = UPB;
    if (nLocal < 0)   nLocal = 0;

    // per-warp unit setup: warp owns local units {warp, warp+8}
    const float* wp[2][4];
    const float* hsBase[2];
    int jj[2], dd_[2], valid[2];
    #pragma unroll
    for (int r=0;r<2;r++) {
        int lu = warp + 8*r;
        valid[r] = (lu < nLocal);
        int u = u0 + (valid[r] ? lu : 0);
        if (u >= NUNITS) u = 0;           // inert blocks: keep pointers in range
        int d = u >> 10;
        int j = u & (DD-1);
        dd_[r] = d; jj[r] = j;
        const float* Wl = Whh + (size_t)(layer*2 + d)*(size_t)GDIM*DD;
        wp[r][0] = Wl + (size_t)(       j)*DD;   // i
        wp[r][1] = Wl + (size_t)(  DD + j)*DD;   // g
        wp[r][2] = Wl + (size_t)(2*DD + j)*DD;   // f
        wp[r][3] = Wl + (size_t)(3*DD + j)*DD;   // o
        hsBase[r] = h_sm + d*BATCH*DD;
    }
    float creg[2] = {0.f, 0.f};   // cell state: lane b holds batch b

    for (int t = 0; t < TT; ++t) {
        const int rb = t & 1;          // read buffer
        const int wb = rb ^ 1;         // write buffer
        // stage h via L2 (other SMs wrote it last step; L1 may be stale)
        for (int i = tid; i < 2*BATCH*DD; i += RTHREADS)
            h_sm[i] = __ldcg(&g_hcur[rb][i]);
        __syncthreads();

        #pragma unroll
        for (int r = 0; r < 2; ++r) {
            if (!valid[r]) continue;
            const float* hs = hsBase[r];
            const float* w0 = wp[r][0];
            const float* w1 = wp[r][1];
            const float* w2 = wp[r][2];
            const float* w3 = wp[r][3];

            float acc[4][4];
            #pragma unroll
            for (int g=0;g<4;g++)
                #pragma unroll
                for (int b=0;b<4;b++) acc[g][b]=0.f;

            #pragma unroll 4
            for (int k = lane; k < DD; k += 32) {
                float h0 = hs[0*DD + k];
                float h1 = hs[1*DD + k];
                float h2 = hs[2*DD + k];
                float h3 = hs[3*DD + k];
                float a0 = __ldg(w0 + k);
                float a1 = __ldg(w1 + k);
                float a2 = __ldg(w2 + k);
                float a3 = __ldg(w3 + k);
                acc[0][0]=fmaf(a0,h0,acc[0][0]); acc[0][1]=fmaf(a0,h1,acc[0][1]);
                acc[0][2]=fmaf(a0,h2,acc[0][2]); acc[0][3]=fmaf(a0,h3,acc[0][3]);
                acc[1][0]=fmaf(a1,h0,acc[1][0]); acc[1][1]=fmaf(a1,h1,acc[1][1]);
                acc[1][2]=fmaf(a1,h2,acc[1][2]); acc[1][3]=fmaf(a1,h3,acc[1][3]);
                acc[2][0]=fmaf(a2,h0,acc[2][0]); acc[2][1]=fmaf(a2,h1,acc[2][1]);
                acc[2][2]=fmaf(a2,h2,acc[2][2]); acc[2][3]=fmaf(a2,h3,acc[2][3]);
                acc[3][0]=fmaf(a3,h0,acc[3][0]); acc[3][1]=fmaf(a3,h1,acc[3][1]);
                acc[3][2]=fmaf(a3,h2,acc[3][2]); acc[3][3]=fmaf(a3,h3,acc[3][3]);
            }
            #pragma unroll
            for (int g=0;g<4;g++)
                #pragma unroll
                for (int b=0;b<4;b++)
                    #pragma unroll
                    for (int off=16; off>0; off>>=1)
                        acc[g][b] += __shfl_xor_sync(0xffffffffu, acc[g][b], off);

            const int d = dd_[r];
            const int j = jj[r];
            if (lane < BATCH) {
                const int bb = lane;
                const float* gxp = g_gx + ((size_t)(d*BATCH + bb)*TT + t)*(size_t)GDIM;
                float pi = acc[0][bb] + gxp[j];
                float pg = acc[1][bb] + gxp[DD   + j];
                float pf = acc[2][bb] + gxp[2*DD + j];
                float po = acc[3][bb] + gxp[3*DD + j];
                float ii = 1.f/(1.f + expf(-pi));
                float gg = tanhf(pg);
                float ff = 1.f/(1.f + expf(-pf));
                float oo = 1.f/(1.f + expf(-po));
                float c  = ff*creg[r] + ii*gg;
                creg[r]  = c;
                float h  = oo * tanhf(c);
                g_hcur[wb][(d*BATCH + bb)*DD + j] = h;
                float* hist = (d == 0) ? g_hL : g_hR;
                hist[((size_t)bb*TT + t)*DD + j] = h;
            }
        }
        __threadfence();
        grid_barrier(&localEpoch);
    }
}

// ---------------- layer-1 input: x[b][t] = [hL[b][t], hR[b][T-1-t]] --------
__global__ void k_concat() {
    int idx = blockIdx.x * blockDim.x + threadIdx.x;    // float4 granularity
    const int total = BATCH*TT*(KINW/4);
    if (idx >= total) return;
    int c   = idx & (KINW/4 - 1);
    int row = idx >> 9;                 // KINW/4 = 512
    int b   = row >> 12;
    int t   = row & (TT-1);
    float4 v;
    if (c < DD/4) {
        v = reinterpret_cast<const float4*>(g_hL + ((size_t)b*TT + t)*DD)[c];
    } else {
        v = reinterpret_cast<const float4*>(g_hR + ((size_t)b*TT + (TT-1-t))*DD)[c - DD/4];
    }
    reinterpret_cast<float4*>(g_x)[idx] = v;
}

// ---------------- attention logits -----------------------------------------
__global__ void k_dots() {
    const int b = blockIdx.x >> 12;
    const int t = blockIdx.x & (TT-1);
    const int tid = threadIdx.x;
    const float* hl  = g_hL + ((size_t)b*TT + t)*DD;
    const float* hll = g_hL + ((size_t)b*TT + (TT-1))*DD;
    const float* hr  = g_hR + ((size_t)b*TT + t)*DD;
    const float* hrl = g_hR + ((size_t)b*TT + (TT-1))*DD;
    float s = 0.f;
    for (int j = tid; j < DD; j += 256)
        s += hl[j]*hll[j] + hr[j]*hrl[j];
    #pragma unroll
    for (int o=16;o>0;o>>=1) s += __shfl_xor_sync(0xffffffffu, s, o);
    __shared__ float red[8];
    if ((tid & 31) == 0) red[tid>>5] = s;
    __syncthreads();
    if (tid == 0) {
        float v = 0.f;
        #pragma unroll
        for (int w=0;w<8;w++) v += red[w];
        g_wv[(size_t)b*TT + t] = v * (1.f/64.f);   // 1/sqrt(4096)
    }
}

// ---------------- softmax per batch -----------------------------------------
__global__ void k_softmax() {
    const int b = blockIdx.x, tid = threadIdx.x;   // 1024 threads
    __shared__ float red[32];
    __shared__ float sval;
    const float* w = g_wv + (size_t)b*TT;
    float m = -1e30f;
    for (int t = tid; t < TT; t += 1024) m = fmaxf(m, w[t]);
    #pragma unroll
    for (int o=16;o>0;o>>=1) m = fmaxf(m, __shfl_xor_sync(0xffffffffu, m, o));
    if ((tid&31)==0) red[tid>>5] = m;
    __syncthreads();
    if (tid < 32) {
        float v = red[tid];
        #pragma unroll
        for (int o=16;o>0;o>>=1) v = fmaxf(v, __shfl_xor_sync(0xffffffffu, v, o));
        if (tid==0) sval = v;
    }
    __syncthreads();
    m = sval;
    float s = 0.f;
    for (int t = tid; t < TT; t += 1024) {
        float e = expf(w[t] - m);
        g_att[(size_t)b*TT + t] = e;
        s += e;
    }
    #pragma unroll
    for (int o=16;o>0;o>>=1) s += __shfl_xor_sync(0xffffffffu, s, o);
    __syncthreads();
    if ((tid&31)==0) red[tid>>5] = s;
    __syncthreads();
    if (tid < 32) {
        float v = red[tid];
        #pragma unroll
        for (int o=16;o>0;o>>=1) v += __shfl_xor_sync(0xffffffffu, v, o);
        if (tid==0) sval = v;
    }
    __syncthreads();
    float inv = 1.f / sval;
    for (int t = tid; t < TT; t += 1024)
        g_att[(size_t)b*TT + t] *= inv;
}

// ---------------- context vectors -------------------------------------------
__global__ void k_ctxt() {
    const int b = blockIdx.y;
    const int j = blockIdx.x*128 + threadIdx.x;
    const float* att = g_att + (size_t)b*TT;
    float aL = 0.f, aR = 0.f;
    for (int t = 0; t < TT; t += 4) {
        float a0 = att[t], a1 = att[t+1], a2 = att[t+2], a3 = att[t+3];
        const float* hl = g_hL + ((size_t)b*TT + t)*DD + j;
        const float* hr = g_hR + ((size_t)b*TT + t)*DD + j;
        aL += a0*hl[0] + a1*hl[DD] + a2*hl[2*DD] + a3*hl[3*DD];
        aR += a0*hr[0] + a1*hr[DD] + a2*hr[2*DD] + a3*hr[3*DD];
    }
    g_ctxtL[b*DD + j] = aL;
    g_ctxtR[b*DD + j] = aR;
}

// ---------------- output: out[b][m] = WcyL[m].ctxtL[b] + WcyR[m].ctxtR[b] ---
__global__ void k_out(const float* __restrict__ WcyL, const float* __restrict__ WcyR,
                      float* __restrict__ out) {
    const int b = blockIdx.x;
    const int m = threadIdx.x >> 5;     // 2 warps
    const int lane = threadIdx.x & 31;
    float s = 0.f;
    for (int j = lane; j < DD; j += 32)
        s += WcyL[m*DD + j]*g_ctxtL[b*DD + j] + WcyR[m*DD + j]*g_ctxtR[b*DD + j];
    #pragma unroll
    for (int o=16;o>0;o>>=1) s += __shfl_xor_sync(0xffffffffu, s, o);
    if (lane == 0) out[b*MOUT + m] = s;
}

// ---------------- launcher ---------------------------------------------------
extern "C" void kernel_launch(void* const* d_in, const int* in_sizes, int n_in,
                              void* d_out, int out_size) {
    const int*   toks = (const int*)  d_in[0];
    const float* emb  = (const float*)d_in[1];
    const float* Wxh  = (const float*)d_in[2];
    const float* Whh  = (const float*)d_in[3];
    const float* bxh  = (const float*)d_in[4];
    const float* bhh  = (const float*)d_in[5];
    const float* WcyL = (const float*)d_in[6];
    const float* WcyR = (const float*)d_in[7];
    float* out = (float*)d_out;
    (void)in_sizes; (void)n_in; (void)out_size;

    k_embed<<<(BATCH*TT*(EE/4) + 255)/256, 256>>>(toks, emb);

    for (int layer = 0; layer < 2; ++layer) {
        dim3 ggrid(GDIM/64, (BATCH*TT)/128, 2);
        k_gemm<<<ggrid, 256>>>(Wxh, bxh, bhh, layer);
        k_recur<<<RGRID, RTHREADS>>>(Whh, layer);
        if (layer == 0)
            k_concat<<<(BATCH*TT*(KINW/4) + 255)/256, 256>>>();
    }

    k_dots<<<BATCH*TT, 256>>>();
    k_softmax<<<BATCH, 1024>>>();
    dim3 cgrid(DD/128, BATCH);
    k_ctxt<<<cgrid, 128>>>();
    k_out<<<BATCH, 64>>>(WcyL, WcyR, out);
}

// round 10
// speedup vs baseline: 1.4731x; 1.4731x over previous
#include <cuda_runtime.h>
#include <cuda_fp16.h>
#include <math.h>

// Problem constants
#define BATCH   4
#define TT      4096
#define EE      2048
#define DD      1024
#define GDIM    4096          // 4*DD gate rows
#define MOUT    2
#define KINW    2048          // input width per layer (E for l0, 2*DD for l1)

// Recurrence persistent-kernel config
#define RGRID    148          // <= SM count -> guaranteed co-resident
#define RTHREADS 256
#define NUNITS   (2*DD)       // dirs * D hidden units
#define UPB      ((NUNITS + RGRID - 1)/RGRID)   // 14 units per block

// ---------------- scratch (static device arrays only; no allocation) ------
__device__ __align__(128) float g_x   [BATCH*TT*KINW];      // layer input
__device__ __align__(128) float g_gx  [2u*BATCH*TT*GDIM];   // gate preacts, scan order, both dirs
__device__ __align__(128) float g_hL  [BATCH*TT*DD];
__device__ __align__(128) float g_hR  [BATCH*TT*DD];
__device__ __align__(128) float g_hcur[2][2*BATCH*DD];      // double-buffered current h
__device__ __align__(128) __half2 g_whhc[2*2*1024*512*4];   // fp16 Whh, [ld][j][kp][gate]
__device__ float g_wv  [BATCH*TT];
__device__ float g_att [BATCH*TT];
__device__ float g_ctxtL[BATCH*DD];
__device__ float g_ctxtR[BATCH*DD];
__device__ unsigned int g_barCount;
__device__ unsigned int g_barEpoch;

// ---------------- packed f32x2 FMA helpers ----------------
__device__ __forceinline__ void fma2u(unsigned long long& d, unsigned long long a, unsigned long long b) {
    asm("fma.rn.f32x2 %0, %1, %2, %0;" : "+l"(d) : "l"(a), "l"(b));
}
__device__ __forceinline__ unsigned long long dup2(float v) {
    unsigned long long r; unsigned u = __float_as_uint(v);
    asm("mov.b64 %0, {%1, %1};" : "=l"(r) : "r"(u));
    return r;
}
__device__ __forceinline__ void fma2f(float2& d, float2 a, float2 b) {
    asm("fma.rn.f32x2 %0, %1, %2, %0;"
        : "+l"(reinterpret_cast<unsigned long long&>(d))
        : "l"(reinterpret_cast<unsigned long long&>(a)),
          "l"(reinterpret_cast<unsigned long long&>(b)));
}

// ---------------- scoped release/acquire primitives (no CCTL.IVALL) -------
__device__ __forceinline__ unsigned ld_acq(unsigned* p) {
    unsigned v; asm volatile("ld.acquire.gpu.u32 %0, [%1];" : "=r"(v) : "l"(p) : "memory"); return v;
}
__device__ __forceinline__ void st_rel(unsigned* p, unsigned v) {
    asm volatile("st.release.gpu.u32 [%0], %1;" :: "l"(p), "r"(v) : "memory");
}
__device__ __forceinline__ unsigned atom_add_acqrel(unsigned* p, unsigned v) {
    unsigned old;
    asm volatile("atom.acq_rel.gpu.add.u32 %0, [%1], %2;" : "=r"(old) : "l"(p), "r"(v) : "memory");
    return old;
}

// ---------------- embedding gather ----------------
__global__ void k_embed(const int* __restrict__ toks, const float* __restrict__ emb) {
    int idx = blockIdx.x * blockDim.x + threadIdx.x;      // float4 granularity
    const int total = BATCH*TT*(EE/4);
    if (idx >= total) return;
    int row = idx / (EE/4);
    int c   = idx - row*(EE/4);
    int tok = toks[row];
    reinterpret_cast<float4*>(g_x)[idx] =
        reinterpret_cast<const float4*>(emb + (size_t)tok*EE)[c];
}

// ---------------- Whh -> fp16 gate-interleaved: [ld][j][kp][g] -------------
__global__ void k_wconv(const float* __restrict__ Whh) {
    int idx = blockIdx.x * blockDim.x + threadIdx.x;      // over 2*2*1024*512
    const int total = 2*2*1024*512;
    if (idx >= total) return;
    int kp = idx & 511;
    int j  = (idx >> 9) & 1023;
    int ld = idx >> 19;
    const float* Wl = Whh + (size_t)ld * GDIM * DD;
    __half2* outp = g_whhc + (size_t)idx * 4;
    #pragma unroll
    for (int g = 0; g < 4; ++g) {
        const float* wr = Wl + (size_t)(g*DD + j)*DD + 2*kp;
        outp[g] = __floats2half2_rn(wr[0], wr[1]);
    }
}

// ---------------- gx GEMM: gx[d][b][s][n] = x[b][srow] . W[n] + bias -------
// srow = d ? T-1-s : s  (dir-1 consumes reversed input in scan order)
__global__ __launch_bounds__(256) void k_gemm(const float* __restrict__ Wxh,
                                              const float* __restrict__ bxh,
                                              const float* __restrict__ bhh,
                                              int layer) {
    const int d     = blockIdx.z;
    const int nBase = blockIdx.x * 64;
    const int mBase = blockIdx.y * 128;

    const float* W  = Wxh + (size_t)(layer*2 + d) * GDIM * KINW;
    const float* bx = bxh + (size_t)(layer*2 + d) * GDIM;
    const float* bh = bhh + (size_t)(layer*2 + d) * GDIM;

    __shared__ float As[16][128];
    __shared__ float Bs[16][64];

    const int tid  = threadIdx.x;
    const int aRow = tid >> 1;            // 0..127
    const int aKc  = (tid & 1) * 8;       // 0 or 8
    const int wRow = tid & 63;            // 0..63
    const int wKc  = (tid >> 6) * 4;      // 0,4,8,12

    const int bIdx  = mBase >> 12;        // T=4096: a 128-row tile never crosses batch
    const int sBase = mBase & (TT-1);

    const float* Arow;
    {
        int s    = sBase + aRow;
        int srow = d ? (TT-1-s) : s;
        Arow = g_x + ((size_t)bIdx*TT + srow)*KINW;
    }
    const float* Wrow = W + (size_t)(nBase + wRow)*KINW;

    // accumulators: pair p covers rows ty*8+2p, ty*8+2p+1 (lo, hi)
    unsigned long long accp[4][4];
    #pragma unroll
    for (int p=0;p<4;p++)
        #pragma unroll
        for (int j=0;j<4;j++) accp[p][j] = 0ull;

    const int ty = tid >> 4;   // 0..15, 8 M-rows each
    const int tx = tid & 15;   // 0..15, 4 N-cols each

    float4 ca0 = *reinterpret_cast<const float4*>(Arow + aKc);
    float4 ca1 = *reinterpret_cast<const float4*>(Arow + aKc + 4);
    float4 cw0 = *reinterpret_cast<const float4*>(Wrow + wKc);

    for (int k0 = 0; k0 < KINW; k0 += 16) {
        As[aKc+0][aRow]=ca0.x; As[aKc+1][aRow]=ca0.y; As[aKc+2][aRow]=ca0.z; As[aKc+3][aRow]=ca0.w;
        As[aKc+4][aRow]=ca1.x; As[aKc+5][aRow]=ca1.y; As[aKc+6][aRow]=ca1.z; As[aKc+7][aRow]=ca1.w;
        Bs[wKc+0][wRow]=cw0.x; Bs[wKc+1][wRow]=cw0.y; Bs[wKc+2][wRow]=cw0.z; Bs[wKc+3][wRow]=cw0.w;
        __syncthreads();

        const int kn = (k0 + 16 < KINW) ? (k0 + 16) : 0;   // harmless dummy reload on last iter
        ca0 = *reinterpret_cast<const float4*>(Arow + kn + aKc);
        ca1 = *reinterpret_cast<const float4*>(Arow + kn + aKc + 4);
        cw0 = *reinterpret_cast<const float4*>(Wrow + kn + wKc);

        #pragma unroll
        for (int kk = 0; kk < 16; ++kk) {
            const unsigned long long* ap =
                reinterpret_cast<const unsigned long long*>(&As[kk][ty*8]);
            unsigned long long a0 = ap[0], a1 = ap[1], a2 = ap[2], a3 = ap[3];
            float4 fb = *reinterpret_cast<const float4*>(&Bs[kk][tx*4]);
            unsigned long long b0 = dup2(fb.x), b1 = dup2(fb.y),
                               b2 = dup2(fb.z), b3 = dup2(fb.w);
            fma2u(accp[0][0], a0, b0); fma2u(accp[0][1], a0, b1);
            fma2u(accp[0][2], a0, b2); fma2u(accp[0][3], a0, b3);
            fma2u(accp[1][0], a1, b0); fma2u(accp[1][1], a1, b1);
            fma2u(accp[1][2], a1, b2); fma2u(accp[1][3], a1, b3);
            fma2u(accp[2][0], a2, b0); fma2u(accp[2][1], a2, b1);
            fma2u(accp[2][2], a2, b2); fma2u(accp[2][3], a2, b3);
            fma2u(accp[3][0], a3, b0); fma2u(accp[3][1], a3, b1);
            fma2u(accp[3][2], a3, b2); fma2u(accp[3][3], a3, b3);
        }
        __syncthreads();
    }

    float bias[4];
    #pragma unroll
    for (int j=0;j<4;j++) bias[j] = bx[nBase+tx*4+j] + bh[nBase+tx*4+j];

    #pragma unroll
    for (int i=0;i<8;i++) {
        float v[4];
        #pragma unroll
        for (int j=0;j<4;j++) {
            unsigned long long q = accp[i>>1][j];
            unsigned u = (i & 1) ? (unsigned)(q >> 32) : (unsigned)q;
            v[j] = __uint_as_float(u) + bias[j];
        }
        size_t off = ((size_t)(d*BATCH + bIdx)*TT + sBase + ty*8 + i)*(size_t)GDIM + nBase + tx*4;
        *reinterpret_cast<float4*>(g_gx + off) = make_float4(v[0], v[1], v[2], v[3]);
    }
}

// ---------------- grid-wide software barrier (no L1 invalidate) -----------
__device__ __forceinline__ void grid_barrier(unsigned int* localEpoch) {
    __syncthreads();
    if (threadIdx.x == 0) {
        unsigned int e = *localEpoch;
        if (atom_add_acqrel(&g_barCount, 1u) == RGRID - 1u) {
            g_barCount = 0u;                 // ordered before the release store below
            st_rel(&g_barEpoch, e + 1u);
        } else {
            while (ld_acq(&g_barEpoch) == e) { __nanosleep(64); }
        }
        *localEpoch = e + 1u;
    }
    __syncthreads();
}

// ---------------- persistent biLSTM recurrence over T steps ----------------
__global__ __launch_bounds__(RTHREADS) void k_recur(int layer) {
    __shared__ float h_sm[2*BATCH*DD];   // 32 KB: [d][b][k]
    const int tid  = threadIdx.x;
    const int warp = tid >> 5;
    const int lane = tid & 31;

    unsigned int localEpoch = ld_acq(&g_barEpoch);

    // zero h buffer 0 (read at t=0)
    for (int i = blockIdx.x*RTHREADS + tid; i < 2*BATCH*DD; i += RGRID*RTHREADS)
        g_hcur[0][i] = 0.f;
    grid_barrier(&localEpoch);

    const int u0 = blockIdx.x * UPB;
    int nLocal = NUNITS - u0;
    if (nLocal > UPB) nLocal = UPB;
    if (nLocal < 0)   nLocal = 0;

    // per-warp unit setup: warp owns local units {warp, warp+8}
    const uint4* wq[2];
    const float2* hp2[2];
    int jj[2], dd_[2], valid[2];
    #pragma unroll
    for (int r=0;r<2;r++) {
        int lu = warp + 8*r;
        valid[r] = (lu < nLocal);
        int u = u0 + (valid[r] ? lu : 0);
        if (u >= NUNITS) u = 0;           // inert blocks: keep pointers in range
        int d = u >> 10;
        int j = u & (DD-1);
        dd_[r] = d; jj[r] = j;
        wq[r]  = reinterpret_cast<const uint4*>(
                     g_whhc + ((size_t)((layer*2 + d)*1024 + j) * 512) * 4);
        hp2[r] = reinterpret_cast<const float2*>(h_sm + d*BATCH*DD);
    }
    float creg[2] = {0.f, 0.f};   // cell state: lane b holds batch b

    for (int t = 0; t < TT; ++t) {
        const int rb = t & 1;          // read buffer
        const int wb = rb ^ 1;         // write buffer
        // stage h via L2 (other SMs wrote it last step; L1 may be stale)
        {
            const float4* src = reinterpret_cast<const float4*>(g_hcur[rb]);
            float4* dst = reinterpret_cast<float4*>(h_sm);
            for (int i = tid; i < (2*BATCH*DD)/4; i += RTHREADS)
                dst[i] = __ldcg(src + i);
        }
        __syncthreads();

        #pragma unroll
        for (int r = 0; r < 2; ++r) {
            if (!valid[r]) continue;
            const uint4* w = wq[r];
            const float2* hp = hp2[r];

            float2 acc2[4][4];
            #pragma unroll
            for (int g=0;g<4;g++)
                #pragma unroll
                for (int b=0;b<4;b++) acc2[g][b] = make_float2(0.f, 0.f);

            #pragma unroll
            for (int it = 0; it < 16; ++it) {
                int kp = it*32 + lane;
                uint4 wv = w[kp];                 // 4 gates x half2 (2 k), one LDG.128
                float2 w0 = __half22float2(*reinterpret_cast<__half2*>(&wv.x));
                float2 w1 = __half22float2(*reinterpret_cast<__half2*>(&wv.y));
                float2 w2 = __half22float2(*reinterpret_cast<__half2*>(&wv.z));
                float2 w3 = __half22float2(*reinterpret_cast<__half2*>(&wv.w));
                float2 h0 = hp[0*512 + kp];
                float2 h1 = hp[1*512 + kp];
                float2 h2 = hp[2*512 + kp];
                float2 h3 = hp[3*512 + kp];
                fma2f(acc2[0][0], w0, h0); fma2f(acc2[0][1], w0, h1);
                fma2f(acc2[0][2], w0, h2); fma2f(acc2[0][3], w0, h3);
                fma2f(acc2[1][0], w1, h0); fma2f(acc2[1][1], w1, h1);
                fma2f(acc2[1][2], w1, h2); fma2f(acc2[1][3], w1, h3);
                fma2f(acc2[2][0], w2, h0); fma2f(acc2[2][1], w2, h1);
                fma2f(acc2[2][2], w2, h2); fma2f(acc2[2][3], w2, h3);
                fma2f(acc2[3][0], w3, h0); fma2f(acc2[3][1], w3, h1);
                fma2f(acc2[3][2], w3, h2); fma2f(acc2[3][3], w3, h3);
            }

            float acc[4][4];
            #pragma unroll
            for (int g=0;g<4;g++)
                #pragma unroll
                for (int b=0;b<4;b++) {
                    float s = acc2[g][b].x + acc2[g][b].y;
                    #pragma unroll
                    for (int off=16; off>0; off>>=1)
                        s += __shfl_xor_sync(0xffffffffu, s, off);
                    acc[g][b] = s;
                }

            const int d = dd_[r];
            const int j = jj[r];
            if (lane < BATCH) {
                const int bb = lane;
                const float* gxp = g_gx + ((size_t)(d*BATCH + bb)*TT + t)*(size_t)GDIM;
                float pi = acc[0][bb] + __ldcg(gxp + j);
                float pg = acc[1][bb] + __ldcg(gxp + DD   + j);
                float pf = acc[2][bb] + __ldcg(gxp + 2*DD + j);
                float po = acc[3][bb] + __ldcg(gxp + 3*DD + j);
                float ii = 1.f/(1.f + expf(-pi));
                float gg = tanhf(pg);
                float ff = 1.f/(1.f + expf(-pf));
                float oo = 1.f/(1.f + expf(-po));
                float c  = ff*creg[r] + ii*gg;
                creg[r]  = c;
                float h  = oo * tanhf(c);
                g_hcur[wb][(d*BATCH + bb)*DD + j] = h;
                float* hist = (d == 0) ? g_hL : g_hR;
                hist[((size_t)bb*TT + t)*DD + j] = h;
            }
        }
        grid_barrier(&localEpoch);
    }
}

// ---------------- layer-1 input: x[b][t] = [hL[b][t], hR[b][T-1-t]] --------
__global__ void k_concat() {
    int idx = blockIdx.x * blockDim.x + threadIdx.x;    // float4 granularity
    const int total = BATCH*TT*(KINW/4);
    if (idx >= total) return;
    int c   = idx & (KINW/4 - 1);
    int row = idx >> 9;                 // KINW/4 = 512
    int b   = row >> 12;
    int t   = row & (TT-1);
    float4 v;
    if (c < DD/4) {
        v = reinterpret_cast<const float4*>(g_hL + ((size_t)b*TT + t)*DD)[c];
    } else {
        v = reinterpret_cast<const float4*>(g_hR + ((size_t)b*TT + (TT-1-t))*DD)[c - DD/4];
    }
    reinterpret_cast<float4*>(g_x)[idx] = v;
}

// ---------------- attention logits -----------------------------------------
__global__ void k_dots() {
    const int b = blockIdx.x >> 12;
    const int t = blockIdx.x & (TT-1);
    const int tid = threadIdx.x;
    const float* hl  = g_hL + ((size_t)b*TT + t)*DD;
    const float* hll = g_hL + ((size_t)b*TT + (TT-1))*DD;
    const float* hr  = g_hR + ((size_t)b*TT + t)*DD;
    const float* hrl = g_hR + ((size_t)b*TT + (TT-1))*DD;
    float s = 0.f;
    for (int j = tid; j < DD; j += 256)
        s += hl[j]*hll[j] + hr[j]*hrl[j];
    #pragma unroll
    for (int o=16;o>0;o>>=1) s += __shfl_xor_sync(0xffffffffu, s, o);
    __shared__ float red[8];
    if ((tid & 31) == 0) red[tid>>5] = s;
    __syncthreads();
    if (tid == 0) {
        float v = 0.f;
        #pragma unroll
        for (int w=0;w<8;w++) v += red[w];
        g_wv[(size_t)b*TT + t] = v * (1.f/64.f);   // 1/sqrt(4096)
    }
}

// ---------------- softmax per batch -----------------------------------------
__global__ void k_softmax() {
    const int b = blockIdx.x, tid = threadIdx.x;   // 1024 threads
    __shared__ float red[32];
    __shared__ float sval;
    const float* w = g_wv + (size_t)b*TT;
    float m = -1e30f;
    for (int t = tid; t < TT; t += 1024) m = fmaxf(m, w[t]);
    #pragma unroll
    for (int o=16;o>0;o>>=1) m = fmaxf(m, __shfl_xor_sync(0xffffffffu, m, o));
    if ((tid&31)==0) red[tid>>5] = m;
    __syncthreads();
    if (tid < 32) {
        float v = red[tid];
        #pragma unroll
        for (int o=16;o>0;o>>=1) v = fmaxf(v, __shfl_xor_sync(0xffffffffu, v, o));
        if (tid==0) sval = v;
    }
    __syncthreads();
    m = sval;
    float s = 0.f;
    for (int t = tid; t < TT; t += 1024) {
        float e = expf(w[t] - m);
        g_att[(size_t)b*TT + t] = e;
        s += e;
    }
    #pragma unroll
    for (int o=16;o>0;o>>=1) s += __shfl_xor_sync(0xffffffffu, s, o);
    __syncthreads();
    if ((tid&31)==0) red[tid>>5] = s;
    __syncthreads();
    if (tid < 32) {
        float v = red[tid];
        #pragma unroll
        for (int o=16;o>0;o>>=1) v += __shfl_xor_sync(0xffffffffu, v, o);
        if (tid==0) sval = v;
    }
    __syncthreads();
    float inv = 1.f / sval;
    for (int t = tid; t < TT; t += 1024)
        g_att[(size_t)b*TT + t] *= inv;
}

// ---------------- context vectors -------------------------------------------
__global__ void k_ctxt() {
    const int b = blockIdx.y;
    const int j = blockIdx.x*128 + threadIdx.x;
    const float* att = g_att + (size_t)b*TT;
    float aL = 0.f, aR = 0.f;
    for (int t = 0; t < TT; t += 4) {
        float a0 = att[t], a1 = att[t+1], a2 = att[t+2], a3 = att[t+3];
        const float* hl = g_hL + ((size_t)b*TT + t)*DD + j;
        const float* hr = g_hR + ((size_t)b*TT + t)*DD + j;
        aL += a0*hl[0] + a1*hl[DD] + a2*hl[2*DD] + a3*hl[3*DD];
        aR += a0*hr[0] + a1*hr[DD] + a2*hr[2*DD] + a3*hr[3*DD];
    }
    g_ctxtL[b*DD + j] = aL;
    g_ctxtR[b*DD + j] = aR;
}

// ---------------- output: out[b][m] = WcyL[m].ctxtL[b] + WcyR[m].ctxtR[b] ---
__global__ void k_out(const float* __restrict__ WcyL, const float* __restrict__ WcyR,
                      float* __restrict__ out) {
    const int b = blockIdx.x;
    const int m = threadIdx.x >> 5;     // 2 warps
    const int lane = threadIdx.x & 31;
    float s = 0.f;
    for (int j = lane; j < DD; j += 32)
        s += WcyL[m*DD + j]*g_ctxtL[b*DD + j] + WcyR[m*DD + j]*g_ctxtR[b*DD + j];
    #pragma unroll
    for (int o=16;o>0;o>>=1) s += __shfl_xor_sync(0xffffffffu, s, o);
    if (lane == 0) out[b*MOUT + m] = s;
}

// ---------------- launcher ---------------------------------------------------
extern "C" void kernel_launch(void* const* d_in, const int* in_sizes, int n_in,
                              void* d_out, int out_size) {
    const int*   toks = (const int*)  d_in[0];
    const float* emb  = (const float*)d_in[1];
    const float* Wxh  = (const float*)d_in[2];
    const float* Whh  = (const float*)d_in[3];
    const float* bxh  = (const float*)d_in[4];
    const float* bhh  = (const float*)d_in[5];
    const float* WcyL = (const float*)d_in[6];
    const float* WcyR = (const float*)d_in[7];
    float* out = (float*)d_out;
    (void)in_sizes; (void)n_in; (void)out_size;

    k_embed<<<(BATCH*TT*(EE/4) + 255)/256, 256>>>(toks, emb);
    k_wconv<<<(2*2*1024*512 + 255)/256, 256>>>(Whh);

    for (int layer = 0; layer < 2; ++layer) {
        dim3 ggrid(GDIM/64, (BATCH*TT)/128, 2);
        k_gemm<<<ggrid, 256>>>(Wxh, bxh, bhh, layer);
        k_recur<<<RGRID, RTHREADS>>>(layer);
        if (layer == 0)
            k_concat<<<(BATCH*TT*(KINW/4) + 255)/256, 256>>>();
    }

    k_dots<<<BATCH*TT, 256>>>();
    k_softmax<<<BATCH, 1024>>>();
    dim3 cgrid(DD/128, BATCH);
    k_ctxt<<<cgrid, 128>>>();
    k_out<<<BATCH, 64>>>(WcyL, WcyR, out);
}